// round 3
// baseline (speedup 1.0000x reference)
#include <cuda_runtime.h>
#include <math.h>

#define D_MODEL 1024
#define D_FF    4096
#define NE      8
#define NT      8192            // 4*2048 tokens
#define ROWS_MAX 17408          // 16384 + 8*128 padding
#define NTILES  136             // ROWS_MAX/128

// ---------------- static scratch (no runtime allocation allowed) ----------------
__device__ int   g_topk_idx[NT * 2];
__device__ float g_topk_prob[NT * 2];
__device__ int   g_pos[NT * 2];
__device__ int   g_counts[NE];
__device__ float g_probs_sum[NE];
__device__ int   g_poff[NE + 1];
__device__ int   g_cursor[NE];
__device__ int   g_row_token[ROWS_MAX];
__device__ float g_h[(size_t)ROWS_MAX * D_FF];     // GEMM1 output (relu(x@w1+b1)), fp32
__device__ float g_y[(size_t)ROWS_MAX * D_MODEL];  // GEMM2 output (h@w2), fp32

// ---------------- mma.sync m16n8k8 tf32 ----------------
__device__ __forceinline__ void mma_tf32(float* c, const unsigned* a, const unsigned* b) {
    asm volatile(
        "mma.sync.aligned.m16n8k8.row.col.f32.tf32.tf32.f32 "
        "{%0,%1,%2,%3}, {%4,%5,%6,%7}, {%8,%9}, {%0,%1,%2,%3};\n"
        : "+f"(c[0]), "+f"(c[1]), "+f"(c[2]), "+f"(c[3])
        : "r"(a[0]), "r"(a[1]), "r"(a[2]), "r"(a[3]), "r"(b[0]), "r"(b[1]));
}

// round-to-nearest tf32 (kills the truncation bias that sank round 2)
__device__ __forceinline__ float rna_tf32(float v) {
    float r;
    asm("cvt.rna.tf32.f32 %0, %1;\n" : "=f"(r) : "f"(v));
    return r;
}
__device__ __forceinline__ float4 rna_tf32_4(float4 v) {
    v.x = rna_tf32(v.x); v.y = rna_tf32(v.y);
    v.z = rna_tf32(v.z); v.w = rna_tf32(v.w);
    return v;
}

// ---------------- init ----------------
__global__ void k_init() {
    int i = threadIdx.x;
    if (i < NE) { g_counts[i] = 0; g_probs_sum[i] = 0.f; g_cursor[i] = 0; }
}

// ---------------- router: 1 warp per token ----------------
__global__ void __launch_bounds__(256) k_router(const float* __restrict__ x,
                                                const float* __restrict__ gw,
                                                const float* __restrict__ gb) {
    __shared__ float gws[NE * D_MODEL];   // transposed: gws[e*D + d]
    __shared__ float psum[NE];
    __shared__ int   scnt[NE];
    int tid = threadIdx.x;
    for (int i = tid; i < NE * D_MODEL; i += 256) {
        int d = i >> 3, e = i & 7;
        gws[e * D_MODEL + d] = gw[i];
    }
    if (tid < NE) { psum[tid] = 0.f; scnt[tid] = 0; }
    __syncthreads();

    int lane = tid & 31, warp = tid >> 5;
    int t = blockIdx.x * 8 + warp;
    const float* xr = x + (size_t)t * D_MODEL;

    float acc[NE];
#pragma unroll
    for (int e = 0; e < NE; e++) acc[e] = 0.f;
    for (int i = 0; i < D_MODEL / 32; i++) {
        int d = i * 32 + lane;
        float xv = xr[d];
#pragma unroll
        for (int e = 0; e < NE; e++) acc[e] += xv * gws[e * D_MODEL + d];
    }
#pragma unroll
    for (int e = 0; e < NE; e++)
        for (int off = 16; off > 0; off >>= 1)
            acc[e] += __shfl_xor_sync(0xffffffffu, acc[e], off);

    if (lane == 0) {
        float l[NE], p[NE];
        float m = -1e30f;
#pragma unroll
        for (int e = 0; e < NE; e++) { l[e] = acc[e] + gb[e]; m = fmaxf(m, l[e]); }
        float s = 0.f;
#pragma unroll
        for (int e = 0; e < NE; e++) { p[e] = expf(l[e] - m); s += p[e]; }
        float inv = 1.f / s;
#pragma unroll
        for (int e = 0; e < NE; e++) { p[e] *= inv; atomicAdd(&psum[e], p[e]); }
        int e1 = 0;
#pragma unroll
        for (int e = 1; e < NE; e++) if (p[e] > p[e1]) e1 = e;
        int e2 = -1;
#pragma unroll
        for (int e = 0; e < NE; e++) {
            if (e == e1) continue;
            if (e2 < 0 || p[e] > p[e2]) e2 = e;
        }
        float pr = 1.f / (p[e1] + p[e2]);
        g_topk_idx[2 * t] = e1;     g_topk_idx[2 * t + 1] = e2;
        g_topk_prob[2 * t] = p[e1] * pr; g_topk_prob[2 * t + 1] = p[e2] * pr;
        atomicAdd(&scnt[e1], 1);
        atomicAdd(&scnt[e2], 1);
    }
    __syncthreads();
    if (tid < NE) {
        atomicAdd(&g_probs_sum[tid], psum[tid]);
        atomicAdd(&g_counts[tid], scnt[tid]);
    }
}

// ---------------- stats + padded segment offsets ----------------
__global__ void k_stats(float* __restrict__ out) {
    if (threadIdx.x == 0) {
        int off = 0;
        for (int e = 0; e < NE; e++) {
            g_poff[e] = off;
            off += ((g_counts[e] + 127) >> 7) << 7;
        }
        g_poff[NE] = off;
        float* tail = out + (size_t)NT * D_MODEL;
        for (int e = 0; e < NE; e++) tail[e] = (float)g_counts[e] / (float)(NT * 2);
        float avg[NE], mean = 0.f;
        for (int e = 0; e < NE; e++) { avg[e] = g_probs_sum[e] / (float)NT; mean += avg[e]; }
        mean /= (float)NE;
        float var = 0.f;
        for (int e = 0; e < NE; e++) { float d = avg[e] - mean; var += d * d; }
        tail[NE] = var / (float)(NE - 1);   // ddof=1
    }
}

// ---------------- scatter token slots into permuted rows ----------------
__global__ void k_scatter() {
    int s = blockIdx.x * blockDim.x + threadIdx.x;   // 0..NT*2-1 (exact grid)
    int e = g_topk_idx[s];
    int p = g_poff[e] + atomicAdd(&g_cursor[e], 1);
    g_pos[s] = p;
    g_row_token[p] = s >> 1;
}

// ---------------- tiled GEMM (128x128x16, tf32 mma, double-buffered) ----------------
// FIRST=true : A = gather(x) [K=1024], B = w1, epilogue relu(+b1) -> g_h
// FIRST=false: A = g_h       [K=4096], B = w2, epilogue plain     -> g_y
template <int KDIM, int NDIM, bool FIRST>
__global__ void __launch_bounds__(256, 2) k_gemm(const float* __restrict__ Ag,
                                                 const float* __restrict__ Bg,
                                                 const float* __restrict__ bias) {
    __shared__ float As[2][128 * 20];   // 128 rows, 16 k, stride 20 (conflict-free frags)
    __shared__ float Bs[2][16 * 136];   // 16 k, 128 n, stride 136 (conflict-free frags)

    int row0 = blockIdx.x * 128;
    if (row0 >= g_poff[NE]) return;
    int e = 0;
#pragma unroll
    for (int i = 1; i < NE; i++) if (row0 >= g_poff[i]) e = i;
    const int seg = g_poff[e];
    const int cnt = g_counts[e];
    const int n0 = blockIdx.y * 128;
    const int tid = threadIdx.x;

    // per-thread global A pointers for its two rows (j=0 row, j=1 row+64)
    const int r0 = tid >> 2, r1 = r0 + 64;
    const float* ap0;
    const float* ap1;
    if (FIRST) {
        int ga = row0 + r0, gb_ = row0 + r1;
        int tok0 = (ga - seg < cnt) ? g_row_token[ga] : -1;
        int tok1 = (gb_ - seg < cnt) ? g_row_token[gb_] : -1;
        ap0 = (tok0 >= 0) ? Ag + (size_t)tok0 * KDIM + (tid & 3) * 4 : (const float*)0;
        ap1 = (tok1 >= 0) ? Ag + (size_t)tok1 * KDIM + (tid & 3) * 4 : (const float*)0;
    } else {
        ap0 = g_h + (size_t)(row0 + r0) * KDIM + (tid & 3) * 4;
        ap1 = g_h + (size_t)(row0 + r1) * KDIM + (tid & 3) * 4;
    }
    const float* bp = Bg + (size_t)e * KDIM * NDIM + (size_t)(tid >> 5) * NDIM + n0 + (tid & 31) * 4;

    const int sa = r0 * 20 + (tid & 3) * 4;
    const int sb = (tid >> 5) * 136 + (tid & 31) * 4;

    float acc[4][4][4];
#pragma unroll
    for (int a = 0; a < 4; a++)
#pragma unroll
        for (int b = 0; b < 4; b++)
#pragma unroll
            for (int c = 0; c < 4; c++) acc[a][b][c] = 0.f;

    const int lane = tid & 31, warp = tid >> 5;
    const int wm = warp & 1, wn = warp >> 1;
    const int gid = lane >> 2, ktid = lane & 3;

    const int NKT = KDIM / 16;
    const float4 fz = make_float4(0.f, 0.f, 0.f, 0.f);

    // prefetch stage 0 (round to tf32 RNA at SMEM-store time)
    {
        float4 a0 = ap0 ? *(const float4*)(ap0) : fz;
        float4 a1 = ap1 ? *(const float4*)(ap1) : fz;
        float4 b0 = *(const float4*)(bp);
        float4 b1 = *(const float4*)(bp + (size_t)8 * NDIM);
        *(float4*)&As[0][sa] = rna_tf32_4(a0);
        *(float4*)&As[0][sa + 64 * 20] = rna_tf32_4(a1);
        *(float4*)&Bs[0][sb] = rna_tf32_4(b0);
        *(float4*)&Bs[0][sb + 8 * 136] = rna_tf32_4(b1);
    }
    __syncthreads();

    int buf = 0;
#pragma unroll 1
    for (int kt = 0; kt < NKT; kt++) {
        float4 na0 = fz, na1 = fz, nb0 = fz, nb1 = fz;
        const bool more = (kt + 1 < NKT);
        if (more) {
            int kn = (kt + 1) * 16;
            na0 = ap0 ? *(const float4*)(ap0 + kn) : fz;
            na1 = ap1 ? *(const float4*)(ap1 + kn) : fz;
            nb0 = *(const float4*)(bp + (size_t)kn * NDIM);
            nb1 = *(const float4*)(bp + (size_t)(kn + 8) * NDIM);
        }
        // compute on current buffer
        {
            const float* Asb = As[buf];
            const float* Bsb = Bs[buf];
#pragma unroll
            for (int kk = 0; kk < 16; kk += 8) {
                unsigned a[4][4], b[4][2];
#pragma unroll
                for (int mt = 0; mt < 4; mt++) {
                    int rb_ = wm * 64 + mt * 16;
                    a[mt][0] = __float_as_uint(Asb[(rb_ + gid) * 20 + kk + ktid]);
                    a[mt][1] = __float_as_uint(Asb[(rb_ + gid + 8) * 20 + kk + ktid]);
                    a[mt][2] = __float_as_uint(Asb[(rb_ + gid) * 20 + kk + ktid + 4]);
                    a[mt][3] = __float_as_uint(Asb[(rb_ + gid + 8) * 20 + kk + ktid + 4]);
                }
#pragma unroll
                for (int nt = 0; nt < 4; nt++) {
                    int col = wn * 32 + nt * 8 + gid;
                    b[nt][0] = __float_as_uint(Bsb[(kk + ktid) * 136 + col]);
                    b[nt][1] = __float_as_uint(Bsb[(kk + ktid + 4) * 136 + col]);
                }
#pragma unroll
                for (int mt = 0; mt < 4; mt++)
#pragma unroll
                    for (int nt = 0; nt < 4; nt++) mma_tf32(acc[mt][nt], a[mt], b[nt]);
            }
        }
        if (more) {
            *(float4*)&As[buf ^ 1][sa] = rna_tf32_4(na0);
            *(float4*)&As[buf ^ 1][sa + 64 * 20] = rna_tf32_4(na1);
            *(float4*)&Bs[buf ^ 1][sb] = rna_tf32_4(nb0);
            *(float4*)&Bs[buf ^ 1][sb + 8 * 136] = rna_tf32_4(nb1);
            __syncthreads();
            buf ^= 1;
        }
    }

    // epilogue
#pragma unroll
    for (int mt = 0; mt < 4; mt++) {
        int rr0 = row0 + wm * 64 + mt * 16 + gid;
        int rr1 = rr0 + 8;
#pragma unroll
        for (int nt = 0; nt < 4; nt++) {
            int c = n0 + wn * 32 + nt * 8 + ktid * 2;
            if (FIRST) {
                float bb0 = bias[e * NDIM + c];
                float bb1 = bias[e * NDIM + c + 1];
                float2 v0, v1;
                v0.x = fmaxf(acc[mt][nt][0] + bb0, 0.f);
                v0.y = fmaxf(acc[mt][nt][1] + bb1, 0.f);
                v1.x = fmaxf(acc[mt][nt][2] + bb0, 0.f);
                v1.y = fmaxf(acc[mt][nt][3] + bb1, 0.f);
                *(float2*)&g_h[(size_t)rr0 * D_FF + c] = v0;
                *(float2*)&g_h[(size_t)rr1 * D_FF + c] = v1;
            } else {
                float2 v0, v1;
                v0.x = acc[mt][nt][0];
                v0.y = acc[mt][nt][1];
                v1.x = acc[mt][nt][2];
                v1.y = acc[mt][nt][3];
                *(float2*)&g_y[(size_t)rr0 * D_MODEL + c] = v0;
                *(float2*)&g_y[(size_t)rr1 * D_MODEL + c] = v1;
            }
        }
    }
}

// ---------------- combine: out[t] = sum_k p_k * (y[pos_k] + b2[e_k]) ----------------
__global__ void __launch_bounds__(256) k_combine(const float* __restrict__ b2,
                                                 float* __restrict__ out) {
    int t = blockIdx.x, i = threadIdx.x;
    int e0 = g_topk_idx[2 * t], e1 = g_topk_idx[2 * t + 1];
    float p0 = g_topk_prob[2 * t], p1 = g_topk_prob[2 * t + 1];
    int q0 = g_pos[2 * t], q1 = g_pos[2 * t + 1];
    float4 y0 = *(const float4*)&g_y[(size_t)q0 * D_MODEL + i * 4];
    float4 y1 = *(const float4*)&g_y[(size_t)q1 * D_MODEL + i * 4];
    float4 c0 = *(const float4*)&b2[(size_t)e0 * D_MODEL + i * 4];
    float4 c1 = *(const float4*)&b2[(size_t)e1 * D_MODEL + i * 4];
    float4 o;
    o.x = p0 * (y0.x + c0.x) + p1 * (y1.x + c1.x);
    o.y = p0 * (y0.y + c0.y) + p1 * (y1.y + c1.y);
    o.z = p0 * (y0.z + c0.z) + p1 * (y1.z + c1.z);
    o.w = p0 * (y0.w + c0.w) + p1 * (y1.w + c1.w);
    *(float4*)&out[(size_t)t * D_MODEL + i * 4] = o;
}

// ---------------- launch ----------------
extern "C" void kernel_launch(void* const* d_in, const int* in_sizes, int n_in,
                              void* d_out, int out_size) {
    (void)in_sizes; (void)n_in; (void)out_size;
    const float* x  = (const float*)d_in[0];
    const float* gw = (const float*)d_in[1];
    const float* gb = (const float*)d_in[2];
    const float* w1 = (const float*)d_in[3];
    const float* b1 = (const float*)d_in[4];
    const float* w2 = (const float*)d_in[5];
    const float* b2 = (const float*)d_in[6];
    float* out = (float*)d_out;

    k_init<<<1, 32>>>();
    k_router<<<NT / 8, 256>>>(x, gw, gb);
    k_stats<<<1, 32>>>(out);
    k_scatter<<<(NT * 2) / 256, 256>>>();
    k_gemm<D_MODEL, D_FF, true ><<<dim3(NTILES, D_FF / 128), 256>>>(x, w1, b1);
    k_gemm<D_FF, D_MODEL, false><<<dim3(NTILES, D_MODEL / 128), 256>>>((const float*)0, w2, (const float*)0);
    k_combine<<<NT, 256>>>(b2, out);
}